// round 14
// baseline (speedup 1.0000x reference)
#include <cuda_runtime.h>
#include <cuda_fp16.h>
#include <cstdint>
#include <math.h>

#define BB 4
#define SS 4096
#define HH 1024
#define FF 4096
#define EE 8
#define NTOK (BB*SS)        // 16384
#define NSLOT (NTOK*2)      // 32768

#define BM 128
#define BN 256
#define BKC 64              // halves per chunk (128B rows)
#define NSTAGE 4
#define ASZ 16384           // BM rows * 128B
#define BSZ 32768           // BN rows * 128B
#define STGSZ (ASZ+BSZ)
#define SMEM_DYN (NSTAGE*STGSZ + 256)

#define W1_NT (FF/BN)       // 16
#define W1_NCB (HH/BKC)     // 16
#define W2_NT (HH/BN)       // 4
#define W2_NCB (FF/BKC)     // 64
#define IMGCH 16384         // halves per (tile, kchunk) image block (256n x 64k)

#define PREP_S0 (NTOK/8)                 // 2048 token blocks
#define PREP_S1 (EE*W1_NT*W1_NCB)        // 2048 W1 image blocks
#define PREPA_GRID (PREP_S0+PREP_S1)

// ---------------- scratch ----------------------------------------------------
__device__ int    g_counts[EE];
__device__ int    g_offsets[EE];
__device__ int    g_tlist[EE*NTOK];
__device__ float  g_glist[EE*NTOK];
__device__ __half g_hdd[(size_t)NSLOT * FF];             // fp16 hidden acts
__device__ __half g_xt[(size_t)NTOK * HH];               // fp16 x
__device__ __half g_w1t[(size_t)EE * HH * FF];           // smem-image W1 (fp16)
__device__ __half g_w2t[(size_t)EE * FF * HH];           // smem-image W2 (fp16)

// ---------------- helpers -----------------------------------------------------
__device__ __forceinline__ uint32_t smem_u32(const void* p) {
    uint32_t a;
    asm("{ .reg .u64 t; cvta.to.shared.u64 t, %1; cvt.u32.u64 %0, t; }" : "=r"(a) : "l"(p));
    return a;
}
#define CPA16(dst, src, sz) \
    asm volatile("cp.async.cg.shared.global [%0], [%1], 16, %2;" \
        :: "r"(dst), "l"(src), "r"(sz) : "memory")
#define CPA_COMMIT() asm volatile("cp.async.commit_group;" ::: "memory")
#define CPA_WAIT2()  asm volatile("cp.async.wait_group 2;" ::: "memory")

__device__ __forceinline__ void ldsm4(uint32_t* r, uint32_t a) {
    asm volatile("ldmatrix.sync.aligned.m8n8.x4.shared.b16 {%0,%1,%2,%3}, [%4];"
        : "=r"(r[0]), "=r"(r[1]), "=r"(r[2]), "=r"(r[3]) : "r"(a));
}
__device__ __forceinline__ void mma_f16(float* d, const uint32_t* a, const uint32_t* b) {
    asm volatile("mma.sync.aligned.m16n8k16.row.col.f32.f16.f16.f32 "
        "{%0,%1,%2,%3}, {%4,%5,%6,%7}, {%8,%9}, {%0,%1,%2,%3};"
        : "+f"(d[0]), "+f"(d[1]), "+f"(d[2]), "+f"(d[3])
        : "r"(a[0]), "r"(a[1]), "r"(a[2]), "r"(a[3]), "r"(b[0]), "r"(b[1]));
}
// gelu tanh-approx via sigmoid identity: 0.5v(1+tanh(u)) == v / (1 + e^{-2u})
__device__ __forceinline__ float gelu_fast(float v) {
    float u2 = v * v;
    float inner = 0.7978845608028654f * v * fmaf(0.044715f, u2, 1.0f);
    float s = __expf(-2.0f * inner);
    return __fdividef(v, 1.0f + s);
}

// ---------------- kernel 0: zero expert counts --------------------------------
__global__ void zero_counts() {
    if (threadIdx.x < EE) g_counts[threadIdx.x] = 0;
}

// ---------------- device: weight prep (transpose+cvt fp16 into smem image) -----
// image block (e, tn, c): 256 n-rows x 64 k halves (32KB); elem (n,k):
// halves offset n*64 + ch*8 + (k&7), ch = ((k>>3) ^ (n&7) ^ ((n>>3)&7)) & 7
__device__ __forceinline__ void prep_w_body(
    const float* __restrict__ W, __half* __restrict__ dst, int Kdim, int Ndim,
    int bid, int n)
{
    const int NCk = Kdim >> 6;          // 64-k chunks
    const int NT = Ndim >> 8;
    const int c = bid % NCk;
    const int tmp = bid / NCk;
    const int tn = tmp % NT;
    const int e = tmp / NT;

    const float* src = W + (size_t)e * Kdim * Ndim + (size_t)(c * BKC) * Ndim + tn * 256 + n;
    __half* out = dst + (size_t)bid * IMGCH + (uint32_t)n * 64u;

    __align__(16) __half h[BKC];
#pragma unroll
    for (int kk = 0; kk < BKC; kk++) h[kk] = __float2half_rn(src[(size_t)kk * Ndim]);
#pragma unroll
    for (int ch8 = 0; ch8 < 8; ch8++) {
        uint32_t ch = (uint32_t)((ch8 ^ (n & 7) ^ ((n >> 3) & 7)) & 7);
        *(uint4*)(out + ch * 8) = *(const uint4*)(h + ch8 * 8);
    }
}

// ---------------- kernel 1: prep A (x-cvt + zero-out + router + W1 image) ------
__global__ __launch_bounds__(256) void prep_a(
    const float* __restrict__ x, const float* __restrict__ Wg,
    const float* __restrict__ W1, float* __restrict__ out)
{
    const int bx = blockIdx.x;
    if (bx >= PREP_S0) {
        prep_w_body(W1, g_w1t, HH, FF, bx - PREP_S0, threadIdx.x);
        return;
    }

    // ---- token section: 8 tokens per block, warp per token ----
    __shared__ float sWg[HH * EE];   // 32 KB
    {
        const float4* wg4 = (const float4*)Wg;
        float4* s4 = (float4*)sWg;
#pragma unroll
        for (int i = 0; i < 8; i++) s4[threadIdx.x + i * 256] = wg4[threadIdx.x + i * 256];
    }
    __syncthreads();

    const int warp = threadIdx.x >> 5, lane = threadIdx.x & 31;
    const int token = bx * 8 + warp;
    const float4* x4 = (const float4*)x;
    float4* o4 = (float4*)out;
    uint2* xt2 = (uint2*)g_xt;                // 1 uint2 = 4 halves
    const size_t rowb = (size_t)token * (HH / 4);

    float acc[EE];
#pragma unroll
    for (int e = 0; e < EE; e++) acc[e] = 0.0f;

#pragma unroll
    for (int it = 0; it < 8; it++) {
        const int idx = it * 32 + lane;            // float4 index in row
        float4 xv = x4[rowb + idx];
        o4[rowb + idx] = make_float4(0.f, 0.f, 0.f, 0.f);
        __half2 h01 = __floats2half2_rn(xv.x, xv.y);
        __half2 h23 = __floats2half2_rn(xv.z, xv.w);
        uint2 u;
        u.x = *reinterpret_cast<uint32_t*>(&h01);
        u.y = *reinterpret_cast<uint32_t*>(&h23);
        xt2[rowb + idx] = u;
        const float xs[4] = {xv.x, xv.y, xv.z, xv.w};
#pragma unroll
        for (int j = 0; j < 4; j++) {
            const float xj = xs[j];
            const float* wr = sWg + (idx * 4 + j) * EE;
#pragma unroll
            for (int e = 0; e < EE; e++) acc[e] += xj * wr[e];
        }
    }
#pragma unroll
    for (int off = 16; off > 0; off >>= 1)
#pragma unroll
        for (int e = 0; e < EE; e++)
            acc[e] += __shfl_xor_sync(0xFFFFFFFFu, acc[e], off);

    if (lane == 0) {
        int i0 = 0;
#pragma unroll
        for (int e = 1; e < EE; e++) if (acc[e] > acc[i0]) i0 = e;
        int i1 = (i0 == 0) ? 1 : 0;
#pragma unroll
        for (int e = 0; e < EE; e++)
            if (e != i0 && acc[e] > acc[i1]) i1 = e;
        float p1 = __expf(acc[i1] - acc[i0]);
        float denom = 1.0f + p1;
        float w0 = 1.0f / denom, w1 = p1 / denom;
        int p = atomicAdd(&g_counts[i0], 1);
        g_tlist[i0 * NTOK + p] = token; g_glist[i0 * NTOK + p] = w0;
        p = atomicAdd(&g_counts[i1], 1);
        g_tlist[i1 * NTOK + p] = token; g_glist[i1 * NTOK + p] = w1;
    }
}

// ---------------- kernel 2: offsets --------------------------------------------
__global__ void offsets_kernel() {
    if (threadIdx.x == 0 && blockIdx.x == 0) {
        int s = 0;
        for (int e = 0; e < EE; e++) { g_offsets[e] = s; s += g_counts[e]; }
    }
}

// =============== grouped GEMM: 128x256 tile, BK=64 halves, 512 thr =============
// fp16 operands, fp32 accumulate (m16n8k16). 4-stage cp.async, wait_group 2.
// COMPUTE is software-pipelined: ldsm for K-step ks+1 issued before mma of ks.

#define GEMM_PROLOG3() \
    const int t = threadIdx.x, lane = t & 31, wid = t >> 5; \
    const int warpM = wid & 3, warpN = wid >> 2; \
    extern __shared__ float dyn[]; \
    const uint32_t sbase = (smem_u32(dyn) + 127u) & ~127u; \
    const int frow = t >> 2, fq = t & 3; \
    uint32_t afoff[2]; \
    _Pragma("unroll") \
    for (int i = 0; i < 2; i++) \
        afoff[i] = (uint32_t)frow * 128u + (uint32_t)((((2 * fq + i) ^ (frow & 7)) & 7) << 4); \
    const uint32_t rowA128 = (uint32_t)(warpM * 32 + (lane & 15)) * 128u; \
    uint32_t koffA[4]; \
    _Pragma("unroll") \
    for (int ks = 0; ks < 4; ks++) \
        koffA[ks] = (uint32_t)(((2 * ks + (lane >> 4)) ^ (lane & 7)) << 4); \
    const uint32_t rowB128 = (uint32_t)(warpN * 64 + ((lane >> 4) << 3) + (lane & 7)) * 128u; \
    const uint32_t hB = (uint32_t)((lane >> 3) & 1); \
    uint32_t keyN[4]; \
    _Pragma("unroll") \
    for (int p = 0; p < 4; p++) \
        keyN[p] = (uint32_t)((lane & 7) ^ ((p * 2 + (lane >> 4)) & 7)); \
    uint32_t af[2][2][4]; \
    uint32_t bf[2][4][4]; \
    float acc[2][8][4]; \
    _Pragma("unroll") \
    for (int mt = 0; mt < 2; mt++) \
        _Pragma("unroll") \
        for (int nt = 0; nt < 8; nt++) \
            _Pragma("unroll") \
            for (int q = 0; q < 4; q++) acc[mt][nt][q] = 0.0f;

#define FILL_ASYNC(cc, st) do { \
    const uint32_t A_st = sbase + (uint32_t)(st) * (uint32_t)STGSZ; \
    const uint32_t B_st = A_st + (uint32_t)ASZ; \
    const __half* as_ = aptr + (cc) * BKC + fq * 16; \
    CPA16(A_st + afoff[0], as_,     aszf); \
    CPA16(A_st + afoff[1], as_ + 8, aszf); \
    const uint4* bp_ = (const uint4*)(bscr + (size_t)(cc) * IMGCH) + t; \
    const uint32_t bo_ = B_st + (uint32_t)t * 16u; \
    _Pragma("unroll") \
    for (int i = 0; i < 4; i++) CPA16(bo_ + (uint32_t)i * 8192u, bp_ + i * 512, 16u); \
} while (0)

#define LDFRAG(A_st, B_st, ks, buf) do { \
    _Pragma("unroll") \
    for (int mt_ = 0; mt_ < 2; mt_++) \
        ldsm4(af[buf][mt_], (A_st) + rowA128 + (uint32_t)mt_ * 2048u + koffA[ks]); \
    _Pragma("unroll") \
    for (int p_ = 0; p_ < 4; p_++) \
        ldsm4(bf[buf][p_], (B_st) + rowB128 + (uint32_t)p_ * 2048u + ((((uint32_t)(2 * (ks)) + hB) ^ keyN[p_]) << 4)); \
} while (0)

#define MMA_STEP(buf) do { \
    _Pragma("unroll") \
    for (int mt_ = 0; mt_ < 2; mt_++) \
        _Pragma("unroll") \
        for (int p_ = 0; p_ < 4; p_++) { \
            mma_f16(acc[mt_][2 * p_],     af[buf][mt_], &bf[buf][p_][0]); \
            mma_f16(acc[mt_][2 * p_ + 1], af[buf][mt_], &bf[buf][p_][2]); \
        } \
} while (0)

#define COMPUTE(st) do { \
    const uint32_t A_st = sbase + (uint32_t)(st) * (uint32_t)STGSZ; \
    const uint32_t B_st = A_st + (uint32_t)ASZ; \
    LDFRAG(A_st, B_st, 0, 0); \
    _Pragma("unroll") \
    for (int ks = 0; ks < 4; ks++) { \
        const int cur_ = ks & 1; \
        if (ks < 3) LDFRAG(A_st, B_st, ks + 1, cur_ ^ 1); \
        MMA_STEP(cur_); \
    } \
} while (0)

#define GEMM_MAINLOOP(NC) do { \
    FILL_ASYNC(0, 0); CPA_COMMIT(); \
    FILL_ASYNC(1, 1); CPA_COMMIT(); \
    FILL_ASYNC(2, 2); CPA_COMMIT(); \
    CPA_WAIT2(); __syncthreads(); \
    int sc_ = 0; \
    _Pragma("unroll 1") \
    for (int c = 0; c < (NC); ++c) { \
        const int cn_ = c + 3; \
        if (cn_ < (NC)) FILL_ASYNC(cn_, cn_ & 3); \
        CPA_COMMIT(); \
        COMPUTE(sc_); \
        CPA_WAIT2(); __syncthreads(); \
        sc_ = (sc_ + 1) & 3; \
    } \
} while (0)

// kernel 3: hdd[slot,:] = fp16( gelu( x[token,:] @ W1[e] + b1[e] ) )
//           plus W2-image prep blocks (blockIdx.x == W1_NT column)
__global__ __launch_bounds__(512) void gemm1_mma(
    const float* __restrict__ b1, const float* __restrict__ W2)
{
    if (blockIdx.x == W1_NT) {
        // W2 image prep: 1024 blocks x 512 thr cover 2048 256-wide image blocks
        const int r2 = ((blockIdx.z * (NTOK / BM) + blockIdx.y) << 1) + (threadIdx.x >> 8);
        prep_w_body(W2, g_w2t, FF, HH, r2, threadIdx.x & 255);
        return;
    }

    const int e = blockIdx.z;
    const int count = g_counts[e];
    const int mtile = blockIdx.y * BM;
    if (mtile >= count) return;
    const int off = g_offsets[e];
    const int ntile = blockIdx.x * BN;

    GEMM_PROLOG3();

    const __half* bscr = g_w1t + (size_t)(e * W1_NT + blockIdx.x) * W1_NCB * IMGCH;
    const int m_a = mtile + frow;
    const bool aval = (m_a < count);
    const uint32_t aszf = aval ? 16u : 0u;
    const __half* aptr = aval ? (g_xt + (size_t)g_tlist[e * NTOK + m_a] * HH) : g_xt;

    GEMM_MAINLOOP(HH / BKC);

    const int lg = lane >> 2, lc = lane & 3;
#pragma unroll
    for (int nt = 0; nt < 8; nt++) {
        const int ncol = ntile + warpN * 64 + nt * 8 + lc * 2;
        const float2 bias = *(const float2*)(b1 + (size_t)e * FF + ncol);
#pragma unroll
        for (int mt = 0; mt < 2; mt++) {
            const int m0 = mtile + warpM * 32 + mt * 16 + lg;
            if (m0 < count) {
                *(__half2*)(g_hdd + (size_t)(off + m0) * FF + ncol) =
                    __floats2half2_rn(gelu_fast(acc[mt][nt][0] + bias.x),
                                      gelu_fast(acc[mt][nt][1] + bias.y));
            }
            const int m1 = m0 + 8;
            if (m1 < count) {
                *(__half2*)(g_hdd + (size_t)(off + m1) * FF + ncol) =
                    __floats2half2_rn(gelu_fast(acc[mt][nt][2] + bias.x),
                                      gelu_fast(acc[mt][nt][3] + bias.y));
            }
        }
    }
}

// kernel 4: out[token,:] += gate * ( hdd[slot,:] @ W2[e] + b2[e] )
__global__ __launch_bounds__(512) void gemm2_mma(
    const float* __restrict__ b2, float* __restrict__ out)
{
    const int e = blockIdx.z;
    const int count = g_counts[e];
    const int mtile = blockIdx.y * BM;
    if (mtile >= count) return;
    const int off = g_offsets[e];
    const int ntile = blockIdx.x * BN;

    GEMM_PROLOG3();

    const __half* bscr = g_w2t + (size_t)(e * W2_NT + blockIdx.x) * W2_NCB * IMGCH;
    const int m_a = mtile + frow;
    const bool aval = (m_a < count);
    const uint32_t aszf = aval ? 16u : 0u;
    const __half* aptr = g_hdd + (size_t)(off + (aval ? m_a : 0)) * FF;

    GEMM_MAINLOOP(FF / BKC);

    const int lg = lane >> 2, lc = lane & 3;
#pragma unroll
    for (int mt = 0; mt < 2; mt++) {
#pragma unroll
        for (int half_ = 0; half_ < 2; half_++) {
            const int m = mtile + warpM * 32 + mt * 16 + lg + half_ * 8;
            if (m >= count) continue;
            const int tok = g_tlist[e * NTOK + m];
            const float g = g_glist[e * NTOK + m];
            float* dst = out + (size_t)tok * HH + ntile;
            const float* b2r = b2 + (size_t)e * HH + ntile;
#pragma unroll
            for (int nt = 0; nt < 8; nt++) {
                const int ncol = warpN * 64 + nt * 8 + lc * 2;
                atomicAdd(dst + ncol,     g * (acc[mt][nt][half_ * 2]     + b2r[ncol]));
                atomicAdd(dst + ncol + 1, g * (acc[mt][nt][half_ * 2 + 1] + b2r[ncol + 1]));
            }
        }
    }
}

// ---------------- launcher ------------------------------------------------------
extern "C" void kernel_launch(void* const* d_in, const int* in_sizes, int n_in,
                              void* d_out, int out_size)
{
    const float* x  = (const float*)d_in[0];
    const float* Wg = (const float*)d_in[1];
    const float* W1 = (const float*)d_in[2];
    const float* b1 = (const float*)d_in[3];
    const float* W2 = (const float*)d_in[4];
    const float* b2 = (const float*)d_in[5];
    float* out = (float*)d_out;

    cudaFuncSetAttribute(gemm1_mma, cudaFuncAttributeMaxDynamicSharedMemorySize, SMEM_DYN);
    cudaFuncSetAttribute(gemm2_mma, cudaFuncAttributeMaxDynamicSharedMemorySize, SMEM_DYN);

    zero_counts<<<1, 32>>>();
    prep_a<<<PREPA_GRID, 256>>>(x, Wg, W1, out);
    offsets_kernel<<<1, 32>>>();
    gemm1_mma<<<dim3(W1_NT + 1, NTOK / BM, EE), 512, SMEM_DYN>>>(b1, W2);
    gemm2_mma<<<dim3(HH / BN, NTOK / BM, EE), 512, SMEM_DYN>>>(b2, out);
}

// round 16
// speedup vs baseline: 1.0509x; 1.0509x over previous
#include <cuda_runtime.h>
#include <cuda_fp16.h>
#include <cstdint>
#include <math.h>

#define BB 4
#define SS 4096
#define HH 1024
#define FF 4096
#define EE 8
#define NTOK (BB*SS)        // 16384
#define NSLOT (NTOK*2)      // 32768

#define BM 128
#define BN 256
#define BKC 64              // halves per chunk (128B rows)
#define NSTAGE 4
#define ASZ 16384           // BM rows * 128B
#define BSZ 32768           // BN rows * 128B
#define STGSZ (ASZ+BSZ)
#define SMEM_DYN (NSTAGE*STGSZ + 256)

#define W1_NT (FF/BN)       // 16
#define W1_NCB (HH/BKC)     // 16
#define W2_NT (HH/BN)       // 4
#define W2_NCB (FF/BKC)     // 64
#define IMGCH 16384         // halves per (tile, kchunk) image block (256n x 64k)

#define PREP_S0 (NTOK/8)                 // 2048 token blocks
#define PREP_S1 (EE*W1_NT*W1_NCB)        // 2048 W1 image blocks
#define PREPA_GRID (PREP_S0+PREP_S1)

// ---------------- scratch ----------------------------------------------------
__device__ int      g_counts[EE];
__device__ int      g_offsets[EE];
__device__ int      g_tlist[EE*NTOK];
__device__ float    g_glist[EE*NTOK];
__device__ uint32_t g_tinfo[NTOK*2];                     // (expert<<24)|pos per token-slot
__device__ float    g_tgate[NTOK*2];
__device__ __half   g_hdd[(size_t)NSLOT * FF];           // fp16 hidden acts
__device__ __half   g_xt[(size_t)NTOK * HH];             // fp16 x
__device__ __half   g_w1t[(size_t)EE * HH * FF];         // smem-image W1 (fp16)
__device__ __half   g_w2t[(size_t)EE * FF * HH];         // smem-image W2 (fp16)
__device__ float    g_y[(size_t)NSLOT * HH];             // raw gemm2 accumulators

// ---------------- helpers -----------------------------------------------------
__device__ __forceinline__ uint32_t smem_u32(const void* p) {
    uint32_t a;
    asm("{ .reg .u64 t; cvta.to.shared.u64 t, %1; cvt.u32.u64 %0, t; }" : "=r"(a) : "l"(p));
    return a;
}
#define CPA16(dst, src, sz) \
    asm volatile("cp.async.cg.shared.global [%0], [%1], 16, %2;" \
        :: "r"(dst), "l"(src), "r"(sz) : "memory")
#define CPA_COMMIT() asm volatile("cp.async.commit_group;" ::: "memory")
#define CPA_WAIT2()  asm volatile("cp.async.wait_group 2;" ::: "memory")

__device__ __forceinline__ void ldsm4(uint32_t* r, uint32_t a) {
    asm volatile("ldmatrix.sync.aligned.m8n8.x4.shared.b16 {%0,%1,%2,%3}, [%4];"
        : "=r"(r[0]), "=r"(r[1]), "=r"(r[2]), "=r"(r[3]) : "r"(a));
}
__device__ __forceinline__ void mma_f16(float* d, const uint32_t* a, const uint32_t* b) {
    asm volatile("mma.sync.aligned.m16n8k16.row.col.f32.f16.f16.f32 "
        "{%0,%1,%2,%3}, {%4,%5,%6,%7}, {%8,%9}, {%0,%1,%2,%3};"
        : "+f"(d[0]), "+f"(d[1]), "+f"(d[2]), "+f"(d[3])
        : "r"(a[0]), "r"(a[1]), "r"(a[2]), "r"(a[3]), "r"(b[0]), "r"(b[1]));
}
// gelu tanh-approx via sigmoid identity: 0.5v(1+tanh(u)) == v / (1 + e^{-2u})
__device__ __forceinline__ float gelu_fast(float v) {
    float u2 = v * v;
    float inner = 0.7978845608028654f * v * fmaf(0.044715f, u2, 1.0f);
    float s = __expf(-2.0f * inner);
    return __fdividef(v, 1.0f + s);
}

// ---------------- kernel 0: zero expert counts --------------------------------
__global__ void zero_counts() {
    if (threadIdx.x < EE) g_counts[threadIdx.x] = 0;
}

// ---------------- device: weight prep (transpose+cvt fp16 into smem image) -----
__device__ __forceinline__ void prep_w_body(
    const float* __restrict__ W, __half* __restrict__ dst, int Kdim, int Ndim,
    int bid, int n)
{
    const int NCk = Kdim >> 6;          // 64-k chunks
    const int NT = Ndim >> 8;
    const int c = bid % NCk;
    const int tmp = bid / NCk;
    const int tn = tmp % NT;
    const int e = tmp / NT;

    const float* src = W + (size_t)e * Kdim * Ndim + (size_t)(c * BKC) * Ndim + tn * 256 + n;
    __half* out = dst + (size_t)bid * IMGCH + (uint32_t)n * 64u;

    __align__(16) __half h[BKC];
#pragma unroll
    for (int kk = 0; kk < BKC; kk++) h[kk] = __float2half_rn(src[(size_t)kk * Ndim]);
#pragma unroll
    for (int ch8 = 0; ch8 < 8; ch8++) {
        uint32_t ch = (uint32_t)((ch8 ^ (n & 7) ^ ((n >> 3) & 7)) & 7);
        *(uint4*)(out + ch * 8) = *(const uint4*)(h + ch8 * 8);
    }
}

// ---------------- kernel 1: prep A (x-cvt + router + W1 image) -----------------
__global__ __launch_bounds__(256) void prep_a(
    const float* __restrict__ x, const float* __restrict__ Wg,
    const float* __restrict__ W1)
{
    const int bx = blockIdx.x;
    if (bx >= PREP_S0) {
        prep_w_body(W1, g_w1t, HH, FF, bx - PREP_S0, threadIdx.x);
        return;
    }

    __shared__ float sWg[HH * EE];   // 32 KB
    {
        const float4* wg4 = (const float4*)Wg;
        float4* s4 = (float4*)sWg;
#pragma unroll
        for (int i = 0; i < 8; i++) s4[threadIdx.x + i * 256] = wg4[threadIdx.x + i * 256];
    }
    __syncthreads();

    const int warp = threadIdx.x >> 5, lane = threadIdx.x & 31;
    const int token = bx * 8 + warp;
    const float4* x4 = (const float4*)x;
    uint2* xt2 = (uint2*)g_xt;
    const size_t rowb = (size_t)token * (HH / 4);

    float acc[EE];
#pragma unroll
    for (int e = 0; e < EE; e++) acc[e] = 0.0f;

#pragma unroll
    for (int it = 0; it < 8; it++) {
        const int idx = it * 32 + lane;
        float4 xv = x4[rowb + idx];
        __half2 h01 = __floats2half2_rn(xv.x, xv.y);
        __half2 h23 = __floats2half2_rn(xv.z, xv.w);
        uint2 u;
        u.x = *reinterpret_cast<uint32_t*>(&h01);
        u.y = *reinterpret_cast<uint32_t*>(&h23);
        xt2[rowb + idx] = u;
        const float xs[4] = {xv.x, xv.y, xv.z, xv.w};
#pragma unroll
        for (int j = 0; j < 4; j++) {
            const float xj = xs[j];
            const float* wr = sWg + (idx * 4 + j) * EE;
#pragma unroll
            for (int e = 0; e < EE; e++) acc[e] += xj * wr[e];
        }
    }
#pragma unroll
    for (int off = 16; off > 0; off >>= 1)
#pragma unroll
        for (int e = 0; e < EE; e++)
            acc[e] += __shfl_xor_sync(0xFFFFFFFFu, acc[e], off);

    if (lane == 0) {
        int i0 = 0;
#pragma unroll
        for (int e = 1; e < EE; e++) if (acc[e] > acc[i0]) i0 = e;
        int i1 = (i0 == 0) ? 1 : 0;
#pragma unroll
        for (int e = 0; e < EE; e++)
            if (e != i0 && acc[e] > acc[i1]) i1 = e;
        float p1 = __expf(acc[i1] - acc[i0]);
        float denom = 1.0f + p1;
        float w0 = 1.0f / denom, w1 = p1 / denom;
        int p0_ = atomicAdd(&g_counts[i0], 1);
        g_tlist[i0 * NTOK + p0_] = token; g_glist[i0 * NTOK + p0_] = w0;
        int p1_ = atomicAdd(&g_counts[i1], 1);
        g_tlist[i1 * NTOK + p1_] = token; g_glist[i1 * NTOK + p1_] = w1;
        g_tinfo[token * 2]     = ((uint32_t)i0 << 24) | (uint32_t)p0_;
        g_tgate[token * 2]     = w0;
        g_tinfo[token * 2 + 1] = ((uint32_t)i1 << 24) | (uint32_t)p1_;
        g_tgate[token * 2 + 1] = w1;
    }
}

// ---------------- kernel 2: offsets --------------------------------------------
__global__ void offsets_kernel() {
    if (threadIdx.x == 0 && blockIdx.x == 0) {
        int s = 0;
        for (int e = 0; e < EE; e++) { g_offsets[e] = s; s += g_counts[e]; }
    }
}

// =============== grouped GEMM: 128x256 tile, BK=64 halves, 512 thr =============
// fp16 operands, fp32 accumulate (m16n8k16). 4-stage cp.async, wait_group 2.
// Fills for chunk c+3 are interleaved between K-steps of COMPUTE(c).

#define GEMM_PROLOG3() \
    const int t = threadIdx.x, lane = t & 31, wid = t >> 5; \
    const int warpM = wid & 3, warpN = wid >> 2; \
    extern __shared__ float dyn[]; \
    const uint32_t sbase = (smem_u32(dyn) + 127u) & ~127u; \
    const int frow = t >> 2, fq = t & 3; \
    uint32_t afoff[2]; \
    _Pragma("unroll") \
    for (int i = 0; i < 2; i++) \
        afoff[i] = (uint32_t)frow * 128u + (uint32_t)((((2 * fq + i) ^ (frow & 7)) & 7) << 4); \
    const uint32_t rowA128 = (uint32_t)(warpM * 32 + (lane & 15)) * 128u; \
    uint32_t koffA[4]; \
    _Pragma("unroll") \
    for (int ks = 0; ks < 4; ks++) \
        koffA[ks] = (uint32_t)(((2 * ks + (lane >> 4)) ^ (lane & 7)) << 4); \
    const uint32_t rowB128 = (uint32_t)(warpN * 64 + ((lane >> 4) << 3) + (lane & 7)) * 128u; \
    const uint32_t hB = (uint32_t)((lane >> 3) & 1); \
    uint32_t keyN[4]; \
    _Pragma("unroll") \
    for (int p = 0; p < 4; p++) \
        keyN[p] = (uint32_t)((lane & 7) ^ ((p * 2 + (lane >> 4)) & 7)); \
    float acc[2][8][4]; \
    _Pragma("unroll") \
    for (int mt = 0; mt < 2; mt++) \
        _Pragma("unroll") \
        for (int nt = 0; nt < 8; nt++) \
            _Pragma("unroll") \
            for (int q = 0; q < 4; q++) acc[mt][nt][q] = 0.0f;

#define FILL_ASYNC(cc, st) do { \
    const uint32_t A_f = sbase + (uint32_t)(st) * (uint32_t)STGSZ; \
    const uint32_t B_f = A_f + (uint32_t)ASZ; \
    const __half* as_ = aptr + (cc) * BKC + fq * 16; \
    CPA16(A_f + afoff[0], as_,     aszf); \
    CPA16(A_f + afoff[1], as_ + 8, aszf); \
    const uint4* bp_ = (const uint4*)(bscr + (size_t)(cc) * IMGCH) + t; \
    const uint32_t bo_ = B_f + (uint32_t)t * 16u; \
    _Pragma("unroll") \
    for (int i = 0; i < 4; i++) CPA16(bo_ + (uint32_t)i * 8192u, bp_ + i * 512, 16u); \
} while (0)

// COMPUTE chunk in stage `st`, fills for source-chunk `fcc` into stage `fst`.
// fzA/fzB are cp.async src sizes (0 on tail => zero-fill of a dead stage).
#define CHUNK(st, fst, fcc, fzA, fzB) do { \
    const uint32_t A_st = sbase + (uint32_t)(st) * (uint32_t)STGSZ; \
    const uint32_t B_st = A_st + (uint32_t)ASZ; \
    const uint32_t A_f = sbase + (uint32_t)(fst) * (uint32_t)STGSZ; \
    const uint32_t B_f = A_f + (uint32_t)ASZ; \
    const __half* as_ = aptr + (fcc) * BKC + fq * 16; \
    const uint4* bp_ = (const uint4*)(bscr + (size_t)(fcc) * IMGCH) + t; \
    const uint32_t bo_ = B_f + (uint32_t)t * 16u; \
    _Pragma("unroll") \
    for (int ks = 0; ks < 4; ks++) { \
        uint32_t af[2][4]; \
        _Pragma("unroll") \
        for (int mt_ = 0; mt_ < 2; mt_++) \
            ldsm4(af[mt_], A_st + rowA128 + (uint32_t)mt_ * 2048u + koffA[ks]); \
        uint32_t bf[4][4]; \
        _Pragma("unroll") \
        for (int p_ = 0; p_ < 4; p_++) \
            ldsm4(bf[p_], B_st + rowB128 + (uint32_t)p_ * 2048u + ((((uint32_t)(2 * ks) + hB) ^ keyN[p_]) << 4)); \
        if (ks == 0) { \
            CPA16(A_f + afoff[0], as_,     fzA); \
            CPA16(A_f + afoff[1], as_ + 8, fzA); \
        } else if (ks == 1) { \
            CPA16(bo_,          bp_,       fzB); \
            CPA16(bo_ + 8192u,  bp_ + 512, fzB); \
        } else if (ks == 2) { \
            CPA16(bo_ + 16384u, bp_ + 1024, fzB); \
            CPA16(bo_ + 24576u, bp_ + 1536, fzB); \
        } else { \
            CPA_COMMIT(); \
        } \
        _Pragma("unroll") \
        for (int mt_ = 0; mt_ < 2; mt_++) \
            _Pragma("unroll") \
            for (int p_ = 0; p_ < 4; p_++) { \
                mma_f16(acc[mt_][2 * p_],     af[mt_], &bf[p_][0]); \
                mma_f16(acc[mt_][2 * p_ + 1], af[mt_], &bf[p_][2]); \
            } \
    } \
} while (0)

#define GEMM_MAINLOOP(NC) do { \
    FILL_ASYNC(0, 0); CPA_COMMIT(); \
    FILL_ASYNC(1, 1); CPA_COMMIT(); \
    FILL_ASYNC(2, 2); CPA_COMMIT(); \
    CPA_WAIT2(); __syncthreads(); \
    _Pragma("unroll 1") \
    for (int c = 0; c < (NC); ++c) { \
        const int f_ = c + 3; \
        const int live_ = (f_ < (NC)); \
        CHUNK(c & 3, f_ & 3, live_ ? f_ : (NC) - 1, \
              live_ ? aszf : 0u, live_ ? 16u : 0u); \
        CPA_WAIT2(); __syncthreads(); \
    } \
} while (0)

// kernel 3: hdd[slot,:] = fp16( gelu( x[token,:] @ W1[e] + b1[e] ) )
//           plus W2-image prep blocks (blockIdx.x == W1_NT column)
__global__ __launch_bounds__(512) void gemm1_mma(
    const float* __restrict__ b1, const float* __restrict__ W2)
{
    if (blockIdx.x == W1_NT) {
        const int r2 = ((blockIdx.z * (NTOK / BM) + blockIdx.y) << 1) + (threadIdx.x >> 8);
        prep_w_body(W2, g_w2t, FF, HH, r2, threadIdx.x & 255);
        return;
    }

    const int e = blockIdx.z;
    const int count = g_counts[e];
    const int mtile = blockIdx.y * BM;
    if (mtile >= count) return;
    const int off = g_offsets[e];
    const int ntile = blockIdx.x * BN;

    GEMM_PROLOG3();

    const __half* bscr = g_w1t + (size_t)(e * W1_NT + blockIdx.x) * W1_NCB * IMGCH;
    const int m_a = mtile + frow;
    const bool aval = (m_a < count);
    const uint32_t aszf = aval ? 16u : 0u;
    const __half* aptr = aval ? (g_xt + (size_t)g_tlist[e * NTOK + m_a] * HH) : g_xt;

    GEMM_MAINLOOP(HH / BKC);

    const int lg = lane >> 2, lc = lane & 3;
#pragma unroll
    for (int nt = 0; nt < 8; nt++) {
        const int ncol = ntile + warpN * 64 + nt * 8 + lc * 2;
        const float2 bias = *(const float2*)(b1 + (size_t)e * FF + ncol);
#pragma unroll
        for (int mt = 0; mt < 2; mt++) {
            const int m0 = mtile + warpM * 32 + mt * 16 + lg;
            if (m0 < count) {
                *(__half2*)(g_hdd + (size_t)(off + m0) * FF + ncol) =
                    __floats2half2_rn(gelu_fast(acc[mt][nt][0] + bias.x),
                                      gelu_fast(acc[mt][nt][1] + bias.y));
            }
            const int m1 = m0 + 8;
            if (m1 < count) {
                *(__half2*)(g_hdd + (size_t)(off + m1) * FF + ncol) =
                    __floats2half2_rn(gelu_fast(acc[mt][nt][2] + bias.x),
                                      gelu_fast(acc[mt][nt][3] + bias.y));
            }
        }
    }
}

// kernel 4: g_y[slot,:] = hdd[slot,:] @ W2[e]   (raw accumulators, no bias/gate)
__global__ __launch_bounds__(512) void gemm2_mma()
{
    const int e = blockIdx.z;
    const int count = g_counts[e];
    const int mtile = blockIdx.y * BM;
    if (mtile >= count) return;
    const int off = g_offsets[e];
    const int ntile = blockIdx.x * BN;

    GEMM_PROLOG3();

    const __half* bscr = g_w2t + (size_t)(e * W2_NT + blockIdx.x) * W2_NCB * IMGCH;
    const int m_a = mtile + frow;
    const bool aval = (m_a < count);
    const uint32_t aszf = aval ? 16u : 0u;
    const __half* aptr = g_hdd + (size_t)(off + (aval ? m_a : 0)) * FF;

    GEMM_MAINLOOP(FF / BKC);

    const int lg = lane >> 2, lc = lane & 3;
#pragma unroll
    for (int mt = 0; mt < 2; mt++) {
#pragma unroll
        for (int half_ = 0; half_ < 2; half_++) {
            const int m = mtile + warpM * 32 + mt * 16 + lg + half_ * 8;
            if (m >= count) continue;
            float* yd = g_y + (size_t)(off + m) * HH + ntile;
#pragma unroll
            for (int nt = 0; nt < 8; nt++) {
                const int ncol = warpN * 64 + nt * 8 + lc * 2;
                *(float2*)(yd + ncol) =
                    make_float2(acc[mt][nt][half_ * 2], acc[mt][nt][half_ * 2 + 1]);
            }
        }
    }
}

// kernel 5: out[token,:] = sum over the token's 2 slots of gate*(y + b2[e])
__global__ __launch_bounds__(256) void combine_kernel(
    const float* __restrict__ b2, float* __restrict__ out)
{
    const int token = blockIdx.x;
    const int c4 = threadIdx.x;           // 256 threads x float4 = 1024 cols
    const uint32_t u0 = g_tinfo[token * 2];
    const uint32_t u1 = g_tinfo[token * 2 + 1];
    const float gg0 = g_tgate[token * 2];
    const float gg1 = g_tgate[token * 2 + 1];
    const int e0 = (int)(u0 >> 24), p0 = (int)(u0 & 0xFFFFFFu);
    const int e1 = (int)(u1 >> 24), p1 = (int)(u1 & 0xFFFFFFu);
    const size_t s0 = (size_t)(g_offsets[e0] + p0) * HH + c4 * 4;
    const size_t s1 = (size_t)(g_offsets[e1] + p1) * HH + c4 * 4;
    float4 y0 = *(const float4*)(g_y + s0);
    float4 y1 = *(const float4*)(g_y + s1);
    float4 bb0 = *(const float4*)(b2 + (size_t)e0 * HH + c4 * 4);
    float4 bb1 = *(const float4*)(b2 + (size_t)e1 * HH + c4 * 4);
    float4 o;
    o.x = gg0 * (y0.x + bb0.x) + gg1 * (y1.x + bb1.x);
    o.y = gg0 * (y0.y + bb0.y) + gg1 * (y1.y + bb1.y);
    o.z = gg0 * (y0.z + bb0.z) + gg1 * (y1.z + bb1.z);
    o.w = gg0 * (y0.w + bb0.w) + gg1 * (y1.w + bb1.w);
    *(float4*)(out + (size_t)token * HH + c4 * 4) = o;
}

// ---------------- launcher ------------------------------------------------------
extern "C" void kernel_launch(void* const* d_in, const int* in_sizes, int n_in,
                              void* d_out, int out_size)
{
    const float* x  = (const float*)d_in[0];
    const float* Wg = (const float*)d_in[1];
    const float* W1 = (const float*)d_in[2];
    const float* b1 = (const float*)d_in[3];
    const float* W2 = (const float*)d_in[4];
    const float* b2 = (const float*)d_in[5];
    float* out = (float*)d_out;

    cudaFuncSetAttribute(gemm1_mma, cudaFuncAttributeMaxDynamicSharedMemorySize, SMEM_DYN);
    cudaFuncSetAttribute(gemm2_mma, cudaFuncAttributeMaxDynamicSharedMemorySize, SMEM_DYN);

    zero_counts<<<1, 32>>>();
    prep_a<<<PREPA_GRID, 256>>>(x, Wg, W1);
    offsets_kernel<<<1, 32>>>();
    gemm1_mma<<<dim3(W1_NT + 1, NTOK / BM, EE), 512, SMEM_DYN>>>(b1, W2);
    gemm2_mma<<<dim3(HH / BN, NTOK / BM, EE), 512, SMEM_DYN>>>();
    combine_kernel<<<NTOK, 256>>>(b2, out);
}